// round 13
// baseline (speedup 1.0000x reference)
#include <cuda_runtime.h>
#include <cuda_bf16.h>

#define NB 32
#define TC 256
#define NVOCAB 100
#define ND 384
#define DCH 192          // dims per block (2-way D split)
#define NWARPS 12
#define NTILES 4
#define MAXT 2048
#define FB 4             // frames per warp per group
#define RWIN 26          // |t-center|>26 => z>=6.5 => normalized w < ~1e-9
#define WMAX 56          // (FB-1)+2*RWIN+1 = 56

__device__ __forceinline__ void fma2(unsigned long long& acc,
                                     unsigned long long a,
                                     unsigned long long b) {
    asm("fma.rn.f32x2 %0, %1, %2, %0;" : "+l"(acc) : "l"(a), "l"(b));
}
__device__ __forceinline__ unsigned long long dup2(float x) {
    unsigned long long r;
    asm("mov.b64 %0, {%1, %1};" : "=l"(r) : "f"(x));
    return r;
}

// Single fused kernel, 2-way D split: block (bx, b, h) covers dims
// [h*192, (h+1)*192). Per char, lane reads float4 at off+lane*4 (512B slab)
// and float2 at off+128+lane*2 (256B slab): conflict-free LDS, coalesced STG.
// Warp 0 does the per-batch param prep (shfl-scan) while warps 1..11 stage
// the table slab.
__global__ __launch_bounds__(NWARPS * 32, 2)
void ge_main_kernel(const int* __restrict__ text,
                    const int* __restrict__ durs,
                    const float* __restrict__ embed,
                    float* __restrict__ out, int Tt) {
    extern __shared__ float smem[];
    float* semb     = smem;                      // NVOCAB*DCH (76.8 KB)
    float* s_center = semb + NVOCAB * DCH;       // 256
    float* s_invsig = s_center + TC;             // 256
    float* s_wfac   = s_invsig + TC;             // 256
    int*   s_roff   = (int*)(s_wfac + TC);       // 256
    int*   s_fidx   = s_roff + TC;               // MAXT (8 KB)
    int*   s_td     = s_fidx + MAXT;             // totdur
    float* s_wbuf   = (float*)(s_td + 4);        // NWARPS*FB*WMAX
    int*   s_cbuf   = (int*)(s_wbuf + NWARPS * FB * WMAX); // NWARPS*WMAX

    int tid = threadIdx.x;
    int b = blockIdx.y;
    int h = blockIdx.z;

    if (tid < 32) {
        // ---- in-block prep: warp shfl-scan of durations ----
        int lane = tid;
        const int4* dp = (const int4*)(durs + b * TC + lane * 8);
        int4 da = dp[0], db4 = dp[1];
        int dv[8] = {da.x, da.y, da.z, da.w, db4.x, db4.y, db4.z, db4.w};
        const int4* tp = (const int4*)(text + b * TC + lane * 8);
        int4 ta = tp[0], tb4 = tp[1];
        int tv[8] = {ta.x, ta.y, ta.z, ta.w, tb4.x, tb4.y, tb4.z, tb4.w};

        int lanesum = 0;
        #pragma unroll
        for (int i = 0; i < 8; i++) lanesum += dv[i];
        int incl = lanesum;
        #pragma unroll
        for (int off = 1; off < 32; off <<= 1) {
            int v = __shfl_up_sync(0xffffffffu, incl, off);
            if (lane >= off) incl += v;
        }
        int run = incl - lanesum;                // exclusive prefix

        #pragma unroll
        for (int i = 0; i < 8; i++) {
            int c = lane * 8 + i;
            int d = dv[i];
            float df = (float)d;
            float sig = df * 0.5f + 1e-6f;       // dur/SIGMA_C + EPS
            float is = 1.0f / sig;
            s_center[c] = (float)run + df * 0.5f;
            s_invsig[c] = is;
            s_wfac[c]   = 0.3989422804014327f * is;
            s_roff[c]   = tv[i] * DCH;
            for (int f = run; f < run + d; f++) s_fidx[f] = c;
            run += d;
        }
        if (lane == 31) *s_td = incl;
    } else {
        // ---- warps 1..11 stage the 192-dim table slab ----
        for (int i = tid - 32; i < NVOCAB * 48; i += (NWARPS - 1) * 32) {
            int v = i / 48, c = i - v * 48;
            ((float4*)(semb + v * DCH))[c] =
                *((const float4*)(embed + v * ND + h * DCH) + c);
        }
    }
    __syncthreads();

    int totdur = *s_td;
    int wid = tid >> 5, lane = tid & 31;
    float* wrow4 = s_wbuf + wid * (FB * WMAX);
    int*   coffw = s_cbuf + wid * WMAX;

    for (int t0 = (blockIdx.x * NWARPS + wid) * FB; t0 < Tt;
         t0 += NTILES * NWARPS * FB) {

        int nvalid = totdur - t0;
        if (nvalid > FB) nvalid = FB;

        if (nvalid <= 0) {                       // whole group time-pad -> embed[0]
            float4 e0 = ((const float4*)semb)[lane];
            float2 e1 = ((const float2*)(semb + 128))[lane];
            #pragma unroll
            for (int f = 0; f < FB; f++) {
                int t = t0 + f;
                if (t >= Tt) break;
                float* ob = out + ((size_t)b * Tt + t) * ND + h * DCH;
                ((float4*)ob)[lane] = e0;
                ((float2*)(ob + 128))[lane] = e1;
            }
            continue;
        }

        int lo = s_fidx[max(t0 - RWIN, 0)];
        int hi = s_fidx[min(t0 + FB - 1 + RWIN, totdur - 1)] + 1;
        int win = hi - lo;                       // <= 56

        // ---- weight pass (raw weights) ----
        float tt = (float)t0 + 0.5f;
        float l0 = 0.f, l1 = 0.f, l2 = 0.f, l3 = 0.f;
        for (int j = lane; j < win; j += 32) {
            int c = lo + j;
            float is = s_invsig[c];
            float z0 = (tt - s_center[c]) * is;
            float z1 = z0 + is, z2 = z1 + is, z3 = z2 + is;
            float wf = s_wfac[c];
            float w0 = __expf(-0.5f * z0 * z0) * wf;
            float w1 = __expf(-0.5f * z1 * z1) * wf;
            float w2 = __expf(-0.5f * z2 * z2) * wf;
            float w3 = __expf(-0.5f * z3 * z3) * wf;
            if (1 >= nvalid) w1 = 0.f;
            if (2 >= nvalid) w2 = 0.f;
            if (3 >= nvalid) w3 = 0.f;
            *(float4*)&wrow4[j * 4] = make_float4(w0, w1, w2, w3);
            l0 += w0; l1 += w1; l2 += w2; l3 += w3;
        }
        __syncwarp();
        #pragma unroll
        for (int off = 16; off; off >>= 1) {
            l0 += __shfl_xor_sync(0xffffffffu, l0, off);
            l1 += __shfl_xor_sync(0xffffffffu, l1, off);
            l2 += __shfl_xor_sync(0xffffffffu, l2, off);
            l3 += __shfl_xor_sync(0xffffffffu, l3, off);
        }
        float i0 = 1.0f / (l0 + 1e-6f), i1 = 1.0f / (l1 + 1e-6f);
        float i2 = 1.0f / (l2 + 1e-6f), i3 = 1.0f / (l3 + 1e-6f);

        // ---- normalize + compact ----
        int nact = 0;
        for (int base = 0; base < win; base += 32) {
            int j = base + lane;
            float4 wv;
            int off = 0;
            bool act = false;
            if (j < win) {
                wv = *(float4*)&wrow4[j * 4];
                wv.x *= i0; wv.y *= i1; wv.z *= i2; wv.w *= i3;
                act = (wv.x > 1e-8f) | (wv.y > 1e-8f) |
                      (wv.z > 1e-8f) | (wv.w > 1e-8f);
                off = s_roff[lo + j];
            }
            unsigned mask = __ballot_sync(0xffffffffu, act);
            __syncwarp();
            if (act) {
                int pos = nact + __popc(mask & ((1u << lane) - 1u));
                *(float4*)&wrow4[pos * 4] = wv;   // pos <= j, no clobber
                coffw[pos] = off;
            }
            nact += __popc(mask);
        }
        __syncwarp();

        // ---- branch-free FMA pass: 192 dims = ull2 + ull per lane ----
        unsigned long long A[FB][3];
        #pragma unroll
        for (int f = 0; f < FB; f++) { A[f][0] = 0ULL; A[f][1] = 0ULL; A[f][2] = 0ULL; }

        for (int k = 0; k < nact; k++) {
            float4 wv = *(float4*)&wrow4[k * 4];  // LDS.128 broadcast
            int off = coffw[k];                    // LDS broadcast
            ulonglong2 p = ((const ulonglong2*)(semb + off))[lane];       // 512B slab
            unsigned long long q = ((const unsigned long long*)(semb + off + 128))[lane]; // 256B slab
            unsigned long long W0 = dup2(wv.x), W1 = dup2(wv.y);
            unsigned long long W2 = dup2(wv.z), W3 = dup2(wv.w);
            fma2(A[0][0], W0, p.x); fma2(A[0][1], W0, p.y); fma2(A[0][2], W0, q);
            fma2(A[1][0], W1, p.x); fma2(A[1][1], W1, p.y); fma2(A[1][2], W1, q);
            fma2(A[2][0], W2, p.x); fma2(A[2][1], W2, p.y); fma2(A[2][2], W2, q);
            fma2(A[3][0], W3, p.x); fma2(A[3][1], W3, p.y); fma2(A[3][2], W3, q);
        }
        __syncwarp();   // wrow4/coffw reused next group

        // ---- write (weights pre-normalized; coalesced) ----
        #pragma unroll
        for (int f = 0; f < FB; f++) {
            int t = t0 + f;
            if (t >= Tt) break;
            float* ob = out + ((size_t)b * Tt + t) * ND + h * DCH;
            if (f < nvalid) {
                union { unsigned long long u[2]; float4 v; } cv;
                cv.u[0] = A[f][0];
                cv.u[1] = A[f][1];
                ((float4*)ob)[lane] = cv.v;
                union { unsigned long long u; float2 v; } cw;
                cw.u = A[f][2];
                ((float2*)(ob + 128))[lane] = cw.v;
            } else {      // time-pad frame -> embed[0]
                ((float4*)ob)[lane] = ((const float4*)semb)[lane];
                ((float2*)(ob + 128))[lane] = ((const float2*)(semb + 128))[lane];
            }
        }
    }
}

extern "C" void kernel_launch(void* const* d_in, const int* in_sizes, int n_in,
                              void* d_out, int out_size) {
    const int*   text  = (const int*)d_in[0];
    const int*   durs  = (const int*)d_in[1];
    const float* embed = (const float*)d_in[2];
    float* out = (float*)d_out;

    int Tt = out_size / (NB * ND);

    size_t smem_bytes = (size_t)(NVOCAB * DCH + 3 * TC) * sizeof(float)
                        + (size_t)(TC + MAXT + 4) * sizeof(int)
                        + (size_t)(NWARPS * FB * WMAX) * sizeof(float)
                        + (size_t)(NWARPS * WMAX) * sizeof(int);
    cudaFuncSetAttribute(ge_main_kernel,
                         cudaFuncAttributeMaxDynamicSharedMemorySize,
                         (int)smem_bytes);

    ge_main_kernel<<<dim3(NTILES, NB, 2), NWARPS * 32, smem_bytes>>>(
        text, durs, embed, out, Tt);
}

// round 14
// speedup vs baseline: 1.1000x; 1.1000x over previous
#include <cuda_runtime.h>
#include <cuda_bf16.h>

#define NB 32
#define TC 256
#define NVOCAB 100
#define ND 384
#define DCH 128          // dims per block (3-way D split)
#define NWARPS 16
#define NTILES 3
#define MAXT 2048
#define FB 4             // frames per warp per group
#define RWIN 26          // |t-center|>26 => z>=6.5 => normalized w < ~1e-9
#define WMAX 56          // (FB-1)+2*RWIN+1 = 56
#define WTH 1e-9f        // raw-weight activity threshold (sum >= 0.06 always)

__device__ __forceinline__ void fma2(unsigned long long& acc,
                                     unsigned long long a,
                                     unsigned long long b) {
    asm("fma.rn.f32x2 %0, %1, %2, %0;" : "+l"(acc) : "l"(a), "l"(b));
}
__device__ __forceinline__ unsigned long long dup2(float x) {
    unsigned long long r;
    asm("mov.b64 %0, {%1, %1};" : "=l"(r) : "f"(x));
    return r;
}
__device__ __forceinline__ unsigned long long mul2(unsigned long long a,
                                                   unsigned long long b) {
    unsigned long long r;
    asm("mul.rn.f32x2 %0, %1, %2;" : "=l"(r) : "l"(a), "l"(b));
    return r;
}

// Single fused kernel (R12 structure). Block (bx, b, h) covers dims
// [h*128, (h+1)*128). Warp 0 does per-batch param prep (shfl-scan) while
// warps 1..15 stage the table slab. Weight+compact fused into one pass;
// normalization applied to accumulators in the epilogue.
__global__ __launch_bounds__(NWARPS * 32, 2)
void ge_main_kernel(const int* __restrict__ text,
                    const int* __restrict__ durs,
                    const float* __restrict__ embed,
                    float* __restrict__ out, int Tt) {
    extern __shared__ float smem[];
    float* semb     = smem;                      // NVOCAB*DCH (51.2 KB)
    float* s_center = semb + NVOCAB * DCH;       // 256
    float* s_invsig = s_center + TC;             // 256
    float* s_wfac   = s_invsig + TC;             // 256
    int*   s_roff   = (int*)(s_wfac + TC);       // 256
    int*   s_fidx   = s_roff + TC;               // MAXT (8 KB)
    int*   s_td     = s_fidx + MAXT;             // totdur
    float* s_wbuf   = (float*)(s_td + 4);        // NWARPS*FB*WMAX
    int*   s_cbuf   = (int*)(s_wbuf + NWARPS * FB * WMAX); // NWARPS*WMAX

    int tid = threadIdx.x;
    int b = blockIdx.y;
    int h = blockIdx.z;

    if (tid < 32) {
        // ---- in-block prep: warp shfl-scan of durations ----
        int lane = tid;
        const int4* dp = (const int4*)(durs + b * TC + lane * 8);
        int4 da = dp[0], db4 = dp[1];
        int dv[8] = {da.x, da.y, da.z, da.w, db4.x, db4.y, db4.z, db4.w};
        const int4* tp = (const int4*)(text + b * TC + lane * 8);
        int4 ta = tp[0], tb4 = tp[1];
        int tv[8] = {ta.x, ta.y, ta.z, ta.w, tb4.x, tb4.y, tb4.z, tb4.w};

        int lanesum = 0;
        #pragma unroll
        for (int i = 0; i < 8; i++) lanesum += dv[i];
        int incl = lanesum;
        #pragma unroll
        for (int off = 1; off < 32; off <<= 1) {
            int v = __shfl_up_sync(0xffffffffu, incl, off);
            if (lane >= off) incl += v;
        }
        int run = incl - lanesum;                // exclusive prefix

        #pragma unroll
        for (int i = 0; i < 8; i++) {
            int c = lane * 8 + i;
            int d = dv[i];
            float df = (float)d;
            float sig = df * 0.5f + 1e-6f;       // dur/SIGMA_C + EPS
            float is = 1.0f / sig;
            s_center[c] = (float)run + df * 0.5f;
            s_invsig[c] = is;
            s_wfac[c]   = 0.3989422804014327f * is;
            s_roff[c]   = tv[i] * DCH;
            for (int f = run; f < run + d; f++) s_fidx[f] = c;
            run += d;
        }
        if (lane == 31) *s_td = incl;
    } else {
        // ---- warps 1..15 stage the 128-dim table slab ----
        for (int i = tid - 32; i < NVOCAB * 32; i += (NWARPS - 1) * 32) {
            int v = i >> 5, c = i & 31;
            ((float4*)(semb + v * DCH))[c] =
                *((const float4*)(embed + v * ND + h * DCH) + c);
        }
    }
    __syncthreads();

    int totdur = *s_td;
    int wid = tid >> 5, lane = tid & 31;
    float* wrow4 = s_wbuf + wid * (FB * WMAX);
    int*   coffw = s_cbuf + wid * WMAX;

    for (int t0 = (blockIdx.x * NWARPS + wid) * FB; t0 < Tt;
         t0 += NTILES * NWARPS * FB) {

        int nvalid = totdur - t0;
        if (nvalid > FB) nvalid = FB;

        if (nvalid <= 0) {                       // whole group time-pad -> embed[0]
            float4 e0 = ((const float4*)semb)[lane];
            #pragma unroll
            for (int f = 0; f < FB; f++) {
                int t = t0 + f;
                if (t >= Tt) break;
                ((float4*)(out + ((size_t)b * Tt + t) * ND + h * DCH))[lane] = e0;
            }
            continue;
        }

        int lo = s_fidx[max(t0 - RWIN, 0)];
        int hi = s_fidx[min(t0 + FB - 1 + RWIN, totdur - 1)] + 1;
        int win = hi - lo;                       // <= 56

        // ---- fused weight + compact pass (raw weights, fixed threshold) ----
        float tt = (float)t0 + 0.5f;
        float l0 = 0.f, l1 = 0.f, l2 = 0.f, l3 = 0.f;
        int nact = 0;
        for (int base = 0; base < win; base += 32) {
            int j = base + lane;
            float4 wv;
            int off = 0;
            bool act = false;
            if (j < win) {
                int c = lo + j;
                float is = s_invsig[c];
                float z0 = (tt - s_center[c]) * is;
                float z1 = z0 + is, z2 = z1 + is, z3 = z2 + is;
                float wf = s_wfac[c];
                float w0 = __expf(-0.5f * z0 * z0) * wf;
                float w1 = __expf(-0.5f * z1 * z1) * wf;
                float w2 = __expf(-0.5f * z2 * z2) * wf;
                float w3 = __expf(-0.5f * z3 * z3) * wf;
                if (1 >= nvalid) w1 = 0.f;
                if (2 >= nvalid) w2 = 0.f;
                if (3 >= nvalid) w3 = 0.f;
                wv = make_float4(w0, w1, w2, w3);
                l0 += w0; l1 += w1; l2 += w2; l3 += w3;
                act = (w0 > WTH) | (w1 > WTH) | (w2 > WTH) | (w3 > WTH);
                off = s_roff[c];
            }
            unsigned mask = __ballot_sync(0xffffffffu, act);
            if (act) {
                int pos = nact + __popc(mask & ((1u << lane) - 1u));
                *(float4*)&wrow4[pos * 4] = wv;
                coffw[pos] = off;
            }
            nact += __popc(mask);
        }
        __syncwarp();
        #pragma unroll
        for (int off = 16; off; off >>= 1) {
            l0 += __shfl_xor_sync(0xffffffffu, l0, off);
            l1 += __shfl_xor_sync(0xffffffffu, l1, off);
            l2 += __shfl_xor_sync(0xffffffffu, l2, off);
            l3 += __shfl_xor_sync(0xffffffffu, l3, off);
        }
        float i0 = 1.0f / (l0 + 1e-6f), i1 = 1.0f / (l1 + 1e-6f);
        float i2 = 1.0f / (l2 + 1e-6f), i3 = 1.0f / (l3 + 1e-6f);

        // ---- branch-free FMA pass over raw weights ----
        unsigned long long A[FB][2];
        #pragma unroll
        for (int f = 0; f < FB; f++) { A[f][0] = 0ULL; A[f][1] = 0ULL; }

        for (int k = 0; k < nact; k++) {
            float4 wv = *(float4*)&wrow4[k * 4];  // LDS.128 broadcast
            int off = coffw[k];                    // LDS broadcast
            ulonglong2 p = ((const ulonglong2*)(semb + off))[lane];
            unsigned long long W0 = dup2(wv.x), W1 = dup2(wv.y);
            unsigned long long W2 = dup2(wv.z), W3 = dup2(wv.w);
            fma2(A[0][0], W0, p.x); fma2(A[0][1], W0, p.y);
            fma2(A[1][0], W1, p.x); fma2(A[1][1], W1, p.y);
            fma2(A[2][0], W2, p.x); fma2(A[2][1], W2, p.y);
            fma2(A[3][0], W3, p.x); fma2(A[3][1], W3, p.y);
        }
        __syncwarp();   // wrow4/coffw reused next group

        // ---- scale by 1/sum and write (coalesced 512B) ----
        unsigned long long I[FB] = { dup2(i0), dup2(i1), dup2(i2), dup2(i3) };
        #pragma unroll
        for (int f = 0; f < FB; f++) {
            int t = t0 + f;
            if (t >= Tt) break;
            float4* o = (float4*)(out + ((size_t)b * Tt + t) * ND + h * DCH);
            if (f < nvalid) {
                union { unsigned long long u[2]; float4 v; } cv;
                cv.u[0] = mul2(A[f][0], I[f]);
                cv.u[1] = mul2(A[f][1], I[f]);
                o[lane] = cv.v;
            } else {      // time-pad frame -> embed[0]
                o[lane] = ((const float4*)semb)[lane];
            }
        }
    }
}

extern "C" void kernel_launch(void* const* d_in, const int* in_sizes, int n_in,
                              void* d_out, int out_size) {
    const int*   text  = (const int*)d_in[0];
    const int*   durs  = (const int*)d_in[1];
    const float* embed = (const float*)d_in[2];
    float* out = (float*)d_out;

    int Tt = out_size / (NB * ND);

    size_t smem_bytes = (size_t)(NVOCAB * DCH + 3 * TC) * sizeof(float)
                        + (size_t)(TC + MAXT + 4) * sizeof(int)
                        + (size_t)(NWARPS * FB * WMAX) * sizeof(float)
                        + (size_t)(NWARPS * WMAX) * sizeof(int);
    cudaFuncSetAttribute(ge_main_kernel,
                         cudaFuncAttributeMaxDynamicSharedMemorySize,
                         (int)smem_bytes);

    ge_main_kernel<<<dim3(NTILES, NB, 3), NWARPS * 32, smem_bytes>>>(
        text, durs, embed, out, Tt);
}

// round 15
// speedup vs baseline: 1.1892x; 1.0811x over previous
#include <cuda_runtime.h>
#include <cuda_bf16.h>

#define NB 32
#define TC 256
#define NVOCAB 100
#define ND 384
#define DCH 128          // dims per block (3-way D split)
#define NWARPS 16
#define NTILES 3
#define MAXT 2048
#define FB 4             // frames per warp per group
#define RWIN 26          // |t-center|>26 => z>=6.5 => normalized w < ~1e-9
#define WMAX 56          // (FB-1)+2*RWIN+1 = 56
#define WTH 1e-9f        // raw-weight activity threshold (sum >= 0.06 always)
#define ZS 0.8493218f    // sqrt(0.5*log2(e)) : exp(-z^2/2)=2^(-(z*ZS)^2)

__device__ __forceinline__ void fma2(unsigned long long& acc,
                                     unsigned long long a,
                                     unsigned long long b) {
    asm("fma.rn.f32x2 %0, %1, %2, %0;" : "+l"(acc) : "l"(a), "l"(b));
}
__device__ __forceinline__ unsigned long long dup2(float x) {
    unsigned long long r;
    asm("mov.b64 %0, {%1, %1};" : "=l"(r) : "f"(x));
    return r;
}
__device__ __forceinline__ unsigned long long mul2(unsigned long long a,
                                                   unsigned long long b) {
    unsigned long long r;
    asm("mul.rn.f32x2 %0, %1, %2;" : "=l"(r) : "l"(a), "l"(b));
    return r;
}
__device__ __forceinline__ float ex2(float x) {
    float r;
    asm("ex2.approx.ftz.f32 %0, %1;" : "=f"(r) : "f"(x));
    return r;
}

// Single fused kernel (R12 structure). Block (bx, b, h) covers dims
// [h*128, (h+1)*128). Warp 0 does per-batch param prep (shfl-scan) while
// warps 1..15 stage the table slab. Weight+compact fused; normalizer is the
// truncated sum accumulated inside the FMA loop (no shuffle reduce);
// 1/sum applied to accumulators in the epilogue.
__global__ __launch_bounds__(NWARPS * 32, 2)
void ge_main_kernel(const int* __restrict__ text,
                    const int* __restrict__ durs,
                    const float* __restrict__ embed,
                    float* __restrict__ out, int Tt) {
    extern __shared__ float smem[];
    float* semb     = smem;                      // NVOCAB*DCH (51.2 KB)
    float* s_center = semb + NVOCAB * DCH;       // 256
    float* s_zstep  = s_center + TC;             // 256 (invsig * ZS)
    float* s_wfac   = s_zstep + TC;              // 256
    int*   s_roff   = (int*)(s_wfac + TC);       // 256
    int*   s_fidx   = s_roff + TC;               // MAXT (8 KB)
    int*   s_td     = s_fidx + MAXT;             // totdur
    float* s_wbuf   = (float*)(s_td + 4);        // NWARPS*FB*WMAX
    int*   s_cbuf   = (int*)(s_wbuf + NWARPS * FB * WMAX); // NWARPS*WMAX

    int tid = threadIdx.x;
    int b = blockIdx.y;
    int h = blockIdx.z;

    if (tid < 32) {
        // ---- in-block prep: warp shfl-scan of durations ----
        int lane = tid;
        const int4* dp = (const int4*)(durs + b * TC + lane * 8);
        int4 da = dp[0], db4 = dp[1];
        int dv[8] = {da.x, da.y, da.z, da.w, db4.x, db4.y, db4.z, db4.w};
        const int4* tp = (const int4*)(text + b * TC + lane * 8);
        int4 ta = tp[0], tb4 = tp[1];
        int tv[8] = {ta.x, ta.y, ta.z, ta.w, tb4.x, tb4.y, tb4.z, tb4.w};

        int lanesum = 0;
        #pragma unroll
        for (int i = 0; i < 8; i++) lanesum += dv[i];
        int incl = lanesum;
        #pragma unroll
        for (int off = 1; off < 32; off <<= 1) {
            int v = __shfl_up_sync(0xffffffffu, incl, off);
            if (lane >= off) incl += v;
        }
        int run = incl - lanesum;                // exclusive prefix

        #pragma unroll
        for (int i = 0; i < 8; i++) {
            int c = lane * 8 + i;
            int d = dv[i];
            float df = (float)d;
            float sig = df * 0.5f + 1e-6f;       // dur/SIGMA_C + EPS
            float is = 1.0f / sig;
            s_center[c] = (float)run + df * 0.5f;
            s_zstep[c]  = is * ZS;
            s_wfac[c]   = 0.3989422804014327f * is;
            s_roff[c]   = tv[i] * DCH;
            for (int f = run; f < run + d; f++) s_fidx[f] = c;
            run += d;
        }
        if (lane == 31) *s_td = incl;
    } else {
        // ---- warps 1..15 stage the 128-dim table slab ----
        for (int i = tid - 32; i < NVOCAB * 32; i += (NWARPS - 1) * 32) {
            int v = i >> 5, c = i & 31;
            ((float4*)(semb + v * DCH))[c] =
                *((const float4*)(embed + v * ND + h * DCH) + c);
        }
    }
    __syncthreads();

    int totdur = *s_td;
    int wid = tid >> 5, lane = tid & 31;
    float* wrow4 = s_wbuf + wid * (FB * WMAX);
    int*   coffw = s_cbuf + wid * WMAX;

    for (int t0 = (blockIdx.x * NWARPS + wid) * FB; t0 < Tt;
         t0 += NTILES * NWARPS * FB) {

        int nvalid = totdur - t0;
        if (nvalid > FB) nvalid = FB;

        if (nvalid <= 0) {                       // whole group time-pad -> embed[0]
            float4 e0 = ((const float4*)semb)[lane];
            #pragma unroll
            for (int f = 0; f < FB; f++) {
                int t = t0 + f;
                if (t >= Tt) break;
                ((float4*)(out + ((size_t)b * Tt + t) * ND + h * DCH))[lane] = e0;
            }
            continue;
        }

        int lo = s_fidx[max(t0 - RWIN, 0)];
        int hi = s_fidx[min(t0 + FB - 1 + RWIN, totdur - 1)] + 1;
        int win = hi - lo;                       // <= 56

        // ---- fused weight + compact pass (ex2 weights, no sum here) ----
        float tt = (float)t0 + 0.5f;
        int nact = 0;
        for (int base = 0; base < win; base += 32) {
            int j = base + lane;
            float4 wv;
            int off = 0;
            bool act = false;
            if (j < win) {
                int c = lo + j;
                float zs = s_zstep[c];
                float z0 = (tt - s_center[c]) * zs;  // pre-scaled z
                float z1 = z0 + zs, z2 = z1 + zs, z3 = z2 + zs;
                float wf = s_wfac[c];
                float w0 = ex2(-z0 * z0) * wf;
                float w1 = ex2(-z1 * z1) * wf;
                float w2 = ex2(-z2 * z2) * wf;
                float w3 = ex2(-z3 * z3) * wf;
                if (1 >= nvalid) w1 = 0.f;
                if (2 >= nvalid) w2 = 0.f;
                if (3 >= nvalid) w3 = 0.f;
                wv = make_float4(w0, w1, w2, w3);
                act = (w0 > WTH) | (w1 > WTH) | (w2 > WTH) | (w3 > WTH);
                off = s_roff[c];
            }
            unsigned mask = __ballot_sync(0xffffffffu, act);
            if (act) {
                int pos = nact + __popc(mask & ((1u << lane) - 1u));
                *(float4*)&wrow4[pos * 4] = wv;
                coffw[pos] = off;
            }
            nact += __popc(mask);
        }
        __syncwarp();

        // ---- branch-free FMA pass; sums accumulated in-loop (truncated
        //      normalizer: dropped chars contribute < 1e-9 vs sum >= 0.06) ----
        unsigned long long A[FB][2];
        #pragma unroll
        for (int f = 0; f < FB; f++) { A[f][0] = 0ULL; A[f][1] = 0ULL; }
        float s0 = 0.f, s1 = 0.f, s2 = 0.f, s3 = 0.f;

        for (int k = 0; k < nact; k++) {
            float4 wv = *(float4*)&wrow4[k * 4];  // LDS.128 broadcast
            int off = coffw[k];                    // LDS broadcast
            ulonglong2 p = ((const ulonglong2*)(semb + off))[lane];
            s0 += wv.x; s1 += wv.y; s2 += wv.z; s3 += wv.w;
            unsigned long long W0 = dup2(wv.x), W1 = dup2(wv.y);
            unsigned long long W2 = dup2(wv.z), W3 = dup2(wv.w);
            fma2(A[0][0], W0, p.x); fma2(A[0][1], W0, p.y);
            fma2(A[1][0], W1, p.x); fma2(A[1][1], W1, p.y);
            fma2(A[2][0], W2, p.x); fma2(A[2][1], W2, p.y);
            fma2(A[3][0], W3, p.x); fma2(A[3][1], W3, p.y);
        }
        __syncwarp();   // wrow4/coffw reused next group

        // ---- scale by 1/sum and write (coalesced 512B) ----
        unsigned long long I[FB] = {
            dup2(1.0f / (s0 + 1e-6f)), dup2(1.0f / (s1 + 1e-6f)),
            dup2(1.0f / (s2 + 1e-6f)), dup2(1.0f / (s3 + 1e-6f)) };
        #pragma unroll
        for (int f = 0; f < FB; f++) {
            int t = t0 + f;
            if (t >= Tt) break;
            float4* o = (float4*)(out + ((size_t)b * Tt + t) * ND + h * DCH);
            if (f < nvalid) {
                union { unsigned long long u[2]; float4 v; } cv;
                cv.u[0] = mul2(A[f][0], I[f]);
                cv.u[1] = mul2(A[f][1], I[f]);
                o[lane] = cv.v;
            } else {      // time-pad frame -> embed[0]
                o[lane] = ((const float4*)semb)[lane];
            }
        }
    }
}

extern "C" void kernel_launch(void* const* d_in, const int* in_sizes, int n_in,
                              void* d_out, int out_size) {
    const int*   text  = (const int*)d_in[0];
    const int*   durs  = (const int*)d_in[1];
    const float* embed = (const float*)d_in[2];
    float* out = (float*)d_out;

    int Tt = out_size / (NB * ND);

    size_t smem_bytes = (size_t)(NVOCAB * DCH + 3 * TC) * sizeof(float)
                        + (size_t)(TC + MAXT + 4) * sizeof(int)
                        + (size_t)(NWARPS * FB * WMAX) * sizeof(float)
                        + (size_t)(NWARPS * WMAX) * sizeof(int);
    cudaFuncSetAttribute(ge_main_kernel,
                         cudaFuncAttributeMaxDynamicSharedMemorySize,
                         (int)smem_bytes);

    ge_main_kernel<<<dim3(NTILES, NB, 3), NWARPS * 32, smem_bytes>>>(
        text, durs, embed, out, Tt);
}

// round 16
// speedup vs baseline: 1.1946x; 1.0045x over previous
#include <cuda_runtime.h>
#include <cuda_bf16.h>

#define NB 32
#define TC 256
#define NVOCAB 100
#define ND 384
#define DCH 128          // dims per block (3-way D split)
#define NWARPS 16
#define NTILES 3
#define MAXT 2048
#define FB 4             // frames per warp per group
#define RWIN 26          // |t-center|>26 => z>=6.5 => normalized w < ~1e-9
#define WMAX 56          // (FB-1)+2*RWIN+1 = 56
#define WTH 1e-9f        // raw-weight activity threshold (sum >= 0.06 always)
#define ZS 0.8493218f    // sqrt(0.5*log2(e)) : exp(-z^2/2)=2^(-(z*ZS)^2)

__device__ __forceinline__ void fma2(unsigned long long& acc,
                                     unsigned long long a,
                                     unsigned long long b) {
    asm("fma.rn.f32x2 %0, %1, %2, %0;" : "+l"(acc) : "l"(a), "l"(b));
}
__device__ __forceinline__ unsigned long long dup2(float x) {
    unsigned long long r;
    asm("mov.b64 %0, {%1, %1};" : "=l"(r) : "f"(x));
    return r;
}
__device__ __forceinline__ unsigned long long mul2(unsigned long long a,
                                                   unsigned long long b) {
    unsigned long long r;
    asm("mul.rn.f32x2 %0, %1, %2;" : "=l"(r) : "l"(a), "l"(b));
    return r;
}
__device__ __forceinline__ float ex2(float x) {
    float r;
    asm("ex2.approx.ftz.f32 %0, %1;" : "=f"(r) : "f"(x));
    return r;
}

// Single fused kernel (R15 structure). Weight pass uses a ratio chain:
// w_k = w0 * r * q^(k-1)... with r = 2^{-(2z0+zs)zs} (1 ex2) and
// q = 2^{-2zs^2} precomputed per char -> 2 MUFU/char instead of 4.
__global__ __launch_bounds__(NWARPS * 32, 2)
void ge_main_kernel(const int* __restrict__ text,
                    const int* __restrict__ durs,
                    const float* __restrict__ embed,
                    float* __restrict__ out, int Tt) {
    extern __shared__ float smem[];
    float* semb     = smem;                      // NVOCAB*DCH (51.2 KB)
    float* s_center = semb + NVOCAB * DCH;       // 256
    float* s_zstep  = s_center + TC;             // 256 (invsig * ZS)
    float* s_wfac   = s_zstep + TC;              // 256
    float* s_q      = s_wfac + TC;               // 256 (2^{-2 zs^2})
    int*   s_roff   = (int*)(s_q + TC);          // 256
    int*   s_fidx   = s_roff + TC;               // MAXT (8 KB)
    int*   s_td     = s_fidx + MAXT;             // totdur
    float* s_wbuf   = (float*)(s_td + 4);        // NWARPS*FB*WMAX
    int*   s_cbuf   = (int*)(s_wbuf + NWARPS * FB * WMAX); // NWARPS*WMAX

    int tid = threadIdx.x;
    int b = blockIdx.y;
    int h = blockIdx.z;

    if (tid < 32) {
        // ---- in-block prep: warp shfl-scan of durations ----
        int lane = tid;
        const int4* dp = (const int4*)(durs + b * TC + lane * 8);
        int4 da = dp[0], db4 = dp[1];
        int dv[8] = {da.x, da.y, da.z, da.w, db4.x, db4.y, db4.z, db4.w};
        const int4* tp = (const int4*)(text + b * TC + lane * 8);
        int4 ta = tp[0], tb4 = tp[1];
        int tv[8] = {ta.x, ta.y, ta.z, ta.w, tb4.x, tb4.y, tb4.z, tb4.w};

        int lanesum = 0;
        #pragma unroll
        for (int i = 0; i < 8; i++) lanesum += dv[i];
        int incl = lanesum;
        #pragma unroll
        for (int off = 1; off < 32; off <<= 1) {
            int v = __shfl_up_sync(0xffffffffu, incl, off);
            if (lane >= off) incl += v;
        }
        int run = incl - lanesum;                // exclusive prefix

        #pragma unroll
        for (int i = 0; i < 8; i++) {
            int c = lane * 8 + i;
            int d = dv[i];
            float df = (float)d;
            float sig = df * 0.5f + 1e-6f;       // dur/SIGMA_C + EPS
            float is = 1.0f / sig;
            float zs = is * ZS;
            s_center[c] = (float)run + df * 0.5f;
            s_zstep[c]  = zs;
            s_wfac[c]   = 0.3989422804014327f * is;
            s_q[c]      = ex2(-2.0f * zs * zs);
            s_roff[c]   = tv[i] * DCH;
            for (int f = run; f < run + d; f++) s_fidx[f] = c;
            run += d;
        }
        if (lane == 31) *s_td = incl;
    } else {
        // ---- warps 1..15 stage the 128-dim table slab ----
        for (int i = tid - 32; i < NVOCAB * 32; i += (NWARPS - 1) * 32) {
            int v = i >> 5, c = i & 31;
            ((float4*)(semb + v * DCH))[c] =
                *((const float4*)(embed + v * ND + h * DCH) + c);
        }
    }
    __syncthreads();

    int totdur = *s_td;
    int wid = tid >> 5, lane = tid & 31;
    float* wrow4 = s_wbuf + wid * (FB * WMAX);
    int*   coffw = s_cbuf + wid * WMAX;

    for (int t0 = (blockIdx.x * NWARPS + wid) * FB; t0 < Tt;
         t0 += NTILES * NWARPS * FB) {

        int nvalid = totdur - t0;
        if (nvalid > FB) nvalid = FB;

        if (nvalid <= 0) {                       // whole group time-pad -> embed[0]
            float4 e0v = ((const float4*)semb)[lane];
            #pragma unroll
            for (int f = 0; f < FB; f++) {
                int t = t0 + f;
                if (t >= Tt) break;
                ((float4*)(out + ((size_t)b * Tt + t) * ND + h * DCH))[lane] = e0v;
            }
            continue;
        }

        int lo = s_fidx[max(t0 - RWIN, 0)];
        int hi = s_fidx[min(t0 + FB - 1 + RWIN, totdur - 1)] + 1;
        int win = hi - lo;                       // <= 56

        // ---- fused weight + compact pass (2 ex2/char via ratio chain) ----
        float tt = (float)t0 + 0.5f;
        int nact = 0;
        for (int base = 0; base < win; base += 32) {
            int j = base + lane;
            float4 wv;
            int off = 0;
            bool act = false;
            if (j < win) {
                int c = lo + j;
                float zs = s_zstep[c];
                float z0 = (tt - s_center[c]) * zs;   // pre-scaled z
                float e0 = ex2(-z0 * z0);
                float r  = ex2(-fmaf(z0 + z0, zs, zs * zs)); // 2^{-(2z0+zs)zs}
                float q  = s_q[c];
                float w0 = e0 * s_wfac[c];
                float rq = r * q;
                float w1 = w0 * r;
                float w2 = w1 * rq;
                float w3 = w2 * (rq * q);
                if (1 >= nvalid) w1 = 0.f;
                if (2 >= nvalid) w2 = 0.f;
                if (3 >= nvalid) w3 = 0.f;
                wv = make_float4(w0, w1, w2, w3);
                act = (w0 > WTH) | (w1 > WTH) | (w2 > WTH) | (w3 > WTH);
                off = s_roff[c];
            }
            unsigned mask = __ballot_sync(0xffffffffu, act);
            if (act) {
                int pos = nact + __popc(mask & ((1u << lane) - 1u));
                *(float4*)&wrow4[pos * 4] = wv;
                coffw[pos] = off;
            }
            nact += __popc(mask);
        }
        __syncwarp();

        // ---- branch-free FMA pass; truncated normalizer in-loop ----
        unsigned long long A[FB][2];
        #pragma unroll
        for (int f = 0; f < FB; f++) { A[f][0] = 0ULL; A[f][1] = 0ULL; }
        float s0 = 0.f, s1 = 0.f, s2 = 0.f, s3 = 0.f;

        for (int k = 0; k < nact; k++) {
            float4 wv = *(float4*)&wrow4[k * 4];  // LDS.128 broadcast
            int off = coffw[k];                    // LDS broadcast
            ulonglong2 p = ((const ulonglong2*)(semb + off))[lane];
            s0 += wv.x; s1 += wv.y; s2 += wv.z; s3 += wv.w;
            unsigned long long W0 = dup2(wv.x), W1 = dup2(wv.y);
            unsigned long long W2 = dup2(wv.z), W3 = dup2(wv.w);
            fma2(A[0][0], W0, p.x); fma2(A[0][1], W0, p.y);
            fma2(A[1][0], W1, p.x); fma2(A[1][1], W1, p.y);
            fma2(A[2][0], W2, p.x); fma2(A[2][1], W2, p.y);
            fma2(A[3][0], W3, p.x); fma2(A[3][1], W3, p.y);
        }
        __syncwarp();   // wrow4/coffw reused next group

        // ---- scale by 1/sum and write (coalesced 512B) ----
        unsigned long long I[FB] = {
            dup2(1.0f / (s0 + 1e-6f)), dup2(1.0f / (s1 + 1e-6f)),
            dup2(1.0f / (s2 + 1e-6f)), dup2(1.0f / (s3 + 1e-6f)) };
        #pragma unroll
        for (int f = 0; f < FB; f++) {
            int t = t0 + f;
            if (t >= Tt) break;
            float4* o = (float4*)(out + ((size_t)b * Tt + t) * ND + h * DCH);
            if (f < nvalid) {
                union { unsigned long long u[2]; float4 v; } cv;
                cv.u[0] = mul2(A[f][0], I[f]);
                cv.u[1] = mul2(A[f][1], I[f]);
                o[lane] = cv.v;
            } else {      // time-pad frame -> embed[0]
                o[lane] = ((const float4*)semb)[lane];
            }
        }
    }
}

extern "C" void kernel_launch(void* const* d_in, const int* in_sizes, int n_in,
                              void* d_out, int out_size) {
    const int*   text  = (const int*)d_in[0];
    const int*   durs  = (const int*)d_in[1];
    const float* embed = (const float*)d_in[2];
    float* out = (float*)d_out;

    int Tt = out_size / (NB * ND);

    size_t smem_bytes = (size_t)(NVOCAB * DCH + 4 * TC) * sizeof(float)
                        + (size_t)(TC + MAXT + 4) * sizeof(int)
                        + (size_t)(NWARPS * FB * WMAX) * sizeof(float)
                        + (size_t)(NWARPS * WMAX) * sizeof(int);
    cudaFuncSetAttribute(ge_main_kernel,
                         cudaFuncAttributeMaxDynamicSharedMemorySize,
                         (int)smem_bytes);

    ge_main_kernel<<<dim3(NTILES, NB, 3), NWARPS * 32, smem_bytes>>>(
        text, durs, embed, out, Tt);
}

// round 17
// speedup vs baseline: 1.1964x; 1.0015x over previous
#include <cuda_runtime.h>
#include <cuda_bf16.h>

#define NB 32
#define TC 256
#define NVOCAB 100
#define ND 384
#define DCH 128          // dims per block (3-way D split)
#define NWARPS 16
#define NTILES 3
#define MAXT 2048
#define FB 4             // frames per warp per group
#define RWIN 21          // |t-center|>21 => normalized w < ~2e-5 (worst sigma=4)
#define WMAX 48          // (FB-1)+2*RWIN+1 = 46, padded
#define WTH 3e-7f        // raw-weight cut: normalized < ~5e-6 (sum >= 0.06)
#define ZS 0.8493218f    // sqrt(0.5*log2(e)) : exp(-z^2/2)=2^(-(z*ZS)^2)

__device__ __forceinline__ void fma2(unsigned long long& acc,
                                     unsigned long long a,
                                     unsigned long long b) {
    asm("fma.rn.f32x2 %0, %1, %2, %0;" : "+l"(acc) : "l"(a), "l"(b));
}
__device__ __forceinline__ unsigned long long dup2(float x) {
    unsigned long long r;
    asm("mov.b64 %0, {%1, %1};" : "=l"(r) : "f"(x));
    return r;
}
__device__ __forceinline__ unsigned long long mul2(unsigned long long a,
                                                   unsigned long long b) {
    unsigned long long r;
    asm("mul.rn.f32x2 %0, %1, %2;" : "=l"(r) : "l"(a), "l"(b));
    return r;
}
__device__ __forceinline__ float ex2(float x) {
    float r;
    asm("ex2.approx.ftz.f32 %0, %1;" : "=f"(r) : "f"(x));
    return r;
}

// Single fused kernel (R16 structure, tightened active set).
// Block (bx, b, h) covers dims [h*128, (h+1)*128). Warp 0 does per-batch
// param prep (shfl-scan) while warps 1..15 stage the table slab.
__global__ __launch_bounds__(NWARPS * 32, 2)
void ge_main_kernel(const int* __restrict__ text,
                    const int* __restrict__ durs,
                    const float* __restrict__ embed,
                    float* __restrict__ out, int Tt) {
    extern __shared__ float smem[];
    float* semb     = smem;                      // NVOCAB*DCH (51.2 KB)
    float* s_center = semb + NVOCAB * DCH;       // 256
    float* s_zstep  = s_center + TC;             // 256 (invsig * ZS)
    float* s_wfac   = s_zstep + TC;              // 256
    float* s_q      = s_wfac + TC;               // 256 (2^{-2 zs^2})
    int*   s_roff   = (int*)(s_q + TC);          // 256
    int*   s_fidx   = s_roff + TC;               // MAXT (8 KB)
    int*   s_td     = s_fidx + MAXT;             // totdur
    float* s_wbuf   = (float*)(s_td + 4);        // NWARPS*FB*WMAX
    int*   s_cbuf   = (int*)(s_wbuf + NWARPS * FB * WMAX); // NWARPS*WMAX

    int tid = threadIdx.x;
    int b = blockIdx.y;
    int h = blockIdx.z;

    if (tid < 32) {
        // ---- in-block prep: warp shfl-scan of durations ----
        int lane = tid;
        const int4* dp = (const int4*)(durs + b * TC + lane * 8);
        int4 da = dp[0], db4 = dp[1];
        int dv[8] = {da.x, da.y, da.z, da.w, db4.x, db4.y, db4.z, db4.w};
        const int4* tp = (const int4*)(text + b * TC + lane * 8);
        int4 ta = tp[0], tb4 = tp[1];
        int tv[8] = {ta.x, ta.y, ta.z, ta.w, tb4.x, tb4.y, tb4.z, tb4.w};

        int lanesum = 0;
        #pragma unroll
        for (int i = 0; i < 8; i++) lanesum += dv[i];
        int incl = lanesum;
        #pragma unroll
        for (int off = 1; off < 32; off <<= 1) {
            int v = __shfl_up_sync(0xffffffffu, incl, off);
            if (lane >= off) incl += v;
        }
        int run = incl - lanesum;                // exclusive prefix

        #pragma unroll
        for (int i = 0; i < 8; i++) {
            int c = lane * 8 + i;
            int d = dv[i];
            float df = (float)d;
            float sig = df * 0.5f + 1e-6f;       // dur/SIGMA_C + EPS
            float is = 1.0f / sig;
            float zs = is * ZS;
            s_center[c] = (float)run + df * 0.5f;
            s_zstep[c]  = zs;
            s_wfac[c]   = 0.3989422804014327f * is;
            s_q[c]      = ex2(-2.0f * zs * zs);
            s_roff[c]   = tv[i] * DCH;
            for (int f = run; f < run + d; f++) s_fidx[f] = c;
            run += d;
        }
        if (lane == 31) *s_td = incl;
    } else {
        // ---- warps 1..15 stage the 128-dim table slab ----
        for (int i = tid - 32; i < NVOCAB * 32; i += (NWARPS - 1) * 32) {
            int v = i >> 5, c = i & 31;
            ((float4*)(semb + v * DCH))[c] =
                *((const float4*)(embed + v * ND + h * DCH) + c);
        }
    }
    __syncthreads();

    int totdur = *s_td;
    int wid = tid >> 5, lane = tid & 31;
    float* wrow4 = s_wbuf + wid * (FB * WMAX);
    int*   coffw = s_cbuf + wid * WMAX;

    for (int t0 = (blockIdx.x * NWARPS + wid) * FB; t0 < Tt;
         t0 += NTILES * NWARPS * FB) {

        int nvalid = totdur - t0;
        if (nvalid > FB) nvalid = FB;

        if (nvalid <= 0) {                       // whole group time-pad -> embed[0]
            float4 e0v = ((const float4*)semb)[lane];
            #pragma unroll
            for (int f = 0; f < FB; f++) {
                int t = t0 + f;
                if (t >= Tt) break;
                ((float4*)(out + ((size_t)b * Tt + t) * ND + h * DCH))[lane] = e0v;
            }
            continue;
        }

        int lo = s_fidx[max(t0 - RWIN, 0)];
        int hi = s_fidx[min(t0 + FB - 1 + RWIN, totdur - 1)] + 1;
        int win = hi - lo;                       // <= 46

        // ---- fused weight + compact pass (2 ex2/char via ratio chain) ----
        float tt = (float)t0 + 0.5f;
        int nact = 0;
        for (int base = 0; base < win; base += 32) {
            int j = base + lane;
            float4 wv;
            int off = 0;
            bool act = false;
            if (j < win) {
                int c = lo + j;
                float zs = s_zstep[c];
                float z0 = (tt - s_center[c]) * zs;   // pre-scaled z
                float e0 = ex2(-z0 * z0);
                float r  = ex2(-fmaf(z0 + z0, zs, zs * zs)); // 2^{-(2z0+zs)zs}
                float q  = s_q[c];
                float w0 = e0 * s_wfac[c];
                float rq = r * q;
                float w1 = w0 * r;
                float w2 = w1 * rq;
                float w3 = w2 * (rq * q);
                if (1 >= nvalid) w1 = 0.f;
                if (2 >= nvalid) w2 = 0.f;
                if (3 >= nvalid) w3 = 0.f;
                wv = make_float4(w0, w1, w2, w3);
                act = (w0 > WTH) | (w1 > WTH) | (w2 > WTH) | (w3 > WTH);
                off = s_roff[c];
            }
            unsigned mask = __ballot_sync(0xffffffffu, act);
            if (act) {
                int pos = nact + __popc(mask & ((1u << lane) - 1u));
                *(float4*)&wrow4[pos * 4] = wv;
                coffw[pos] = off;
            }
            nact += __popc(mask);
        }
        __syncwarp();

        // ---- branch-free FMA pass; truncated normalizer in-loop ----
        unsigned long long A[FB][2];
        #pragma unroll
        for (int f = 0; f < FB; f++) { A[f][0] = 0ULL; A[f][1] = 0ULL; }
        float s0 = 0.f, s1 = 0.f, s2 = 0.f, s3 = 0.f;

        for (int k = 0; k < nact; k++) {
            float4 wv = *(float4*)&wrow4[k * 4];  // LDS.128 broadcast
            int off = coffw[k];                    // LDS broadcast
            ulonglong2 p = ((const ulonglong2*)(semb + off))[lane];
            s0 += wv.x; s1 += wv.y; s2 += wv.z; s3 += wv.w;
            unsigned long long W0 = dup2(wv.x), W1 = dup2(wv.y);
            unsigned long long W2 = dup2(wv.z), W3 = dup2(wv.w);
            fma2(A[0][0], W0, p.x); fma2(A[0][1], W0, p.y);
            fma2(A[1][0], W1, p.x); fma2(A[1][1], W1, p.y);
            fma2(A[2][0], W2, p.x); fma2(A[2][1], W2, p.y);
            fma2(A[3][0], W3, p.x); fma2(A[3][1], W3, p.y);
        }
        __syncwarp();   // wrow4/coffw reused next group

        // ---- scale by 1/sum and write (coalesced 512B) ----
        unsigned long long I[FB] = {
            dup2(1.0f / (s0 + 1e-6f)), dup2(1.0f / (s1 + 1e-6f)),
            dup2(1.0f / (s2 + 1e-6f)), dup2(1.0f / (s3 + 1e-6f)) };
        #pragma unroll
        for (int f = 0; f < FB; f++) {
            int t = t0 + f;
            if (t >= Tt) break;
            float4* o = (float4*)(out + ((size_t)b * Tt + t) * ND + h * DCH);
            if (f < nvalid) {
                union { unsigned long long u[2]; float4 v; } cv;
                cv.u[0] = mul2(A[f][0], I[f]);
                cv.u[1] = mul2(A[f][1], I[f]);
                o[lane] = cv.v;
            } else {      // time-pad frame -> embed[0]
                o[lane] = ((const float4*)semb)[lane];
            }
        }
    }
}

extern "C" void kernel_launch(void* const* d_in, const int* in_sizes, int n_in,
                              void* d_out, int out_size) {
    const int*   text  = (const int*)d_in[0];
    const int*   durs  = (const int*)d_in[1];
    const float* embed = (const float*)d_in[2];
    float* out = (float*)d_out;

    int Tt = out_size / (NB * ND);

    size_t smem_bytes = (size_t)(NVOCAB * DCH + 4 * TC) * sizeof(float)
                        + (size_t)(TC + MAXT + 4) * sizeof(int)
                        + (size_t)(NWARPS * FB * WMAX) * sizeof(float)
                        + (size_t)(NWARPS * WMAX) * sizeof(int);
    cudaFuncSetAttribute(ge_main_kernel,
                         cudaFuncAttributeMaxDynamicSharedMemorySize,
                         (int)smem_bytes);

    ge_main_kernel<<<dim3(NTILES, NB, 3), NWARPS * 32, smem_bytes>>>(
        text, durs, embed, out, Tt);
}